// round 1
// baseline (speedup 1.0000x reference)
#include <cuda_runtime.h>

// 81-entry coefficient tensor (3^4 basis over {c^2, c*s, s^2} per qubit),
// .x for output 0, .y for output 1. Written by precompute, read by main.
__device__ float2 g_C[81];

// ---------------------------------------------------------------------------
// Precompute: build U (16x16 complex) from shared weights, fold head_w/head_b
// into two real symmetric 16x16 forms, then collapse onto the 81-coef tensor.
// One block, 256 threads; runs in a few microseconds.
// ---------------------------------------------------------------------------
__global__ void precompute_kernel(const float* __restrict__ w,
                                  const float* __restrict__ hw,
                                  const float* __restrict__ hb) {
    __shared__ float ur[16][16];
    __shared__ float ui[16][16];
    __shared__ float2 Cs[81];
    const int t = threadIdx.x;           // 0..255
    const int r = t >> 4, c = t & 15;

    ur[r][c] = (r == c) ? 1.0f : 0.0f;
    ui[r][c] = 0.0f;
    if (t < 81) Cs[t] = make_float2(0.0f, 0.0f);
    __syncthreads();

    for (int rep = 0; rep < 2; ++rep) {
        for (int i = 0; i < 4; ++i) {
            const int bidx = 3 - i;        // wire i <-> bit (3-i)
            const int bit  = 1 << bidx;
            // ---- RZ(weights[0,i,0]):  U' = diag(e^{-i th/2}, e^{+i th/2}) U
            {
                const float th = w[i * 4 + 0];
                const float cz = cosf(0.5f * th);
                const float sz = sinf(0.5f * th);
                const float szz = (r & bit) ? sz : -sz;
                const float a = ur[r][c], b = ui[r][c];
                ur[r][c] = a * cz - b * szz;
                ui[r][c] = a * szz + b * cz;
            }
            __syncthreads();
            // ---- RY(weights[0,i,1]):  rows r0 (bit=0) / r1 (bit=1) mix
            if (t < 128) {
                const float th = w[i * 4 + 1];
                const float cy = cosf(0.5f * th);
                const float sy = sinf(0.5f * th);
                const int cc = t & 15;
                const int rl = t >> 4;                 // 0..7
                const int lm = bit - 1;
                const int r0 = ((rl & ~lm) << 1) | (rl & lm);
                const int r1 = r0 | bit;
                const float a0r = ur[r0][cc], a0i = ui[r0][cc];
                const float a1r = ur[r1][cc], a1i = ui[r1][cc];
                ur[r0][cc] = cy * a0r - sy * a1r;
                ui[r0][cc] = cy * a0i - sy * a1i;
                ur[r1][cc] = sy * a0r + cy * a1r;
                ui[r1][cc] = sy * a0i + cy * a1i;
            }
            __syncthreads();
        }
        // ---- CNOT(control=wire0/bit8, target=wire1/bit4): swap rows r<->r^4
        //      for rows with bit8 set.
        if (t < 64) {
            const int cc = t & 15;
            const int rl = t >> 4;           // 0..3
            const int ra = 8 + rl, rb = 12 + rl;
            float tr = ur[ra][cc]; ur[ra][cc] = ur[rb][cc]; ur[rb][cc] = tr;
            float ti = ui[ra][cc]; ui[ra][cc] = ui[rb][cc]; ui[rb][cc] = ti;
        }
        __syncthreads();
    }

    // Each thread owns ordered pair (k,m)=(r,c):
    //   H_j[k][m] = sum_row c_j[row] * Re(conj(U[row,k]) U[row,m])
    // with c_j[row] = sum_i head_w[j,i] * (+1 if wire-i bit of row is 0 else -1)
    const int k = r, m = c;
    float h0 = 0.0f, h1 = 0.0f;
    const float hw00 = hw[0], hw01 = hw[1], hw02 = hw[2], hw03 = hw[3];
    const float hw10 = hw[4], hw11 = hw[5], hw12 = hw[6], hw13 = hw[7];
    #pragma unroll
    for (int row = 0; row < 16; ++row) {
        const float s0 = (row & 8) ? -1.0f : 1.0f;
        const float s1 = (row & 4) ? -1.0f : 1.0f;
        const float s2 = (row & 2) ? -1.0f : 1.0f;
        const float s3 = (row & 1) ? -1.0f : 1.0f;
        const float zc0 = hw00 * s0 + hw01 * s1 + hw02 * s2 + hw03 * s3;
        const float zc1 = hw10 * s0 + hw11 * s1 + hw12 * s2 + hw13 * s3;
        const float ov = ur[row][k] * ur[row][m] + ui[row][k] * ui[row][m];
        h0 += zc0 * ov;
        h1 += zc1 * ov;
    }
    // Fold bias into the diagonal (sum of probs == 1 == s^T I s).
    if (k == m) { h0 += hb[0]; h1 += hb[1]; }

    // Map (k,m) -> base-3 tensor index: g_i = k_i + m_i  (00->0, 01/10->1, 11->2)
    int g = 0;
    #pragma unroll
    for (int i = 0; i < 4; ++i) {
        const int sh = 3 - i;
        g = g * 3 + (((k >> sh) & 1) + ((m >> sh) & 1));
    }
    atomicAdd(&Cs[g].x, h0);
    atomicAdd(&Cs[g].y, h1);
    __syncthreads();
    if (t < 81) g_C[t] = Cs[t];
}

// ---------------------------------------------------------------------------
// Main kernel: per sample, 4x sincos -> per-qubit (c^2, cs, s^2) -> 81-term
// tensor contraction against g_C (in shared, broadcast LDS). ~291 FMA/sample.
// ---------------------------------------------------------------------------
__global__ void __launch_bounds__(256)
main_kernel(const float4* __restrict__ x4, float2* __restrict__ out, int B) {
    __shared__ float2 Cs[81];
    if (threadIdx.x < 81) Cs[threadIdx.x] = g_C[threadIdx.x];
    __syncthreads();

    const int b = blockIdx.x * 256 + threadIdx.x;
    if (b >= B) return;

    const float4 xv = x4[b];
    float s0, c0, s1, c1, s2, c2, s3, c3;
    __sincosf(0.5f * xv.x, &s0, &c0);
    __sincosf(0.5f * xv.y, &s1, &c1);
    __sincosf(0.5f * xv.z, &s2, &c2);
    __sincosf(0.5f * xv.w, &s3, &c3);

    const float v0[3] = {c0 * c0, c0 * s0, s0 * s0};
    const float v1[3] = {c1 * c1, c1 * s1, s1 * s1};
    const float v2[3] = {c2 * c2, c2 * s2, s2 * s2};
    const float v3[3] = {c3 * c3, c3 * s3, s3 * s3};

    float t9[9];
    #pragma unroll
    for (int a = 0; a < 3; ++a)
        #pragma unroll
        for (int d = 0; d < 3; ++d)
            t9[a * 3 + d] = v0[a] * v1[d];

    float acc0 = 0.0f, acc1 = 0.0f;
    #pragma unroll
    for (int p = 0; p < 9; ++p) {
        #pragma unroll
        for (int q = 0; q < 3; ++q) {
            const float t27 = t9[p] * v2[q];
            #pragma unroll
            for (int u = 0; u < 3; ++u) {
                const float tv = t27 * v3[u];
                const float2 cc = Cs[(p * 3 + q) * 3 + u];
                acc0 = fmaf(tv, cc.x, acc0);
                acc1 = fmaf(tv, cc.y, acc1);
            }
        }
    }
    out[b] = make_float2(acc0, acc1);
}

extern "C" void kernel_launch(void* const* d_in, const int* in_sizes, int n_in,
                              void* d_out, int out_size) {
    const float* x  = (const float*)d_in[0];   // (B, 4) fp32
    const float* w  = (const float*)d_in[1];   // (2, 4, 4) fp32
    const float* hw = (const float*)d_in[2];   // (2, 4) fp32
    const float* hb = (const float*)d_in[3];   // (2,) fp32

    const int B = in_sizes[0] / 4;

    precompute_kernel<<<1, 256>>>(w, hw, hb);
    const int grid = (B + 255) / 256;
    main_kernel<<<grid, 256>>>((const float4*)x, (float2*)d_out, B);
}